// round 7
// baseline (speedup 1.0000x reference)
#include <cuda_runtime.h>
#include <cuda_bf16.h>
#include <math.h>
#include <stdint.h>

// Problem constants
#define N_SEQ  1024
#define B_SZ   4
#define C_DIM  1024
#define H_NUM  16
#define HD     64
#define BH     64          // B*H
#define M_ROWS 4096        // N*B
#define CW     512         // 32-bit words per C_DIM row of packed bf16
#define LOGMAX 4.6051701859880913680f  // log(100)
#define LOG2E  1.4426950408889634f

// Scratch (static device arrays -- no allocations allowed)
__device__ float g_qs[BH * N_SEQ * HD];  // fp32 [bh][n][d] (pre-norm q)
__device__ float g_ks[BH * N_SEQ * HD];

// Pre-split bf16 hi/lo packed words (2 bf16 per uint32)
__device__ uint32_t g_inh[3 * M_ROWS * CW];  // q,k,v inputs [z][m][w]
__device__ uint32_t g_inl[3 * M_ROWS * CW];
__device__ uint32_t g_wih[3 * 1024 * CW];    // in_proj_w
__device__ uint32_t g_wil[3 * 1024 * CW];
__device__ uint32_t g_woh[1024 * CW];        // out_w
__device__ uint32_t g_wol[1024 * CW];
__device__ uint32_t g_xh[M_ROWS * CW];       // attention output (N,B,C)
__device__ uint32_t g_xl[M_ROWS * CW];

// Attention operands
__device__ uint32_t g_qh[BH * N_SEQ * 32];   // normalized q/k [bh][n][dword]
__device__ uint32_t g_ql[BH * N_SEQ * 32];
__device__ uint32_t g_kh[BH * N_SEQ * 32];
__device__ uint32_t g_kl[BH * N_SEQ * 32];
__device__ __align__(16) __nv_bfloat16 g_vh16[BH * HD * N_SEQ];  // [bh][d][n] V^T hi
__device__ __align__(16) __nv_bfloat16 g_vl16[BH * HD * N_SEQ];  // lo

// ---------------------------------------------------------------------------
// Helpers (plain-target PTX only)
// ---------------------------------------------------------------------------
__device__ __forceinline__ void mma_bf16(float* d, const uint32_t* a,
                                         uint32_t b0, uint32_t b1) {
    asm volatile(
        "mma.sync.aligned.m16n8k16.row.col.f32.bf16.bf16.f32 "
        "{%0,%1,%2,%3}, {%4,%5,%6,%7}, {%8,%9}, {%0,%1,%2,%3};"
        : "+f"(d[0]), "+f"(d[1]), "+f"(d[2]), "+f"(d[3])
        : "r"(a[0]), "r"(a[1]), "r"(a[2]), "r"(a[3]), "r"(b0), "r"(b1));
}

__device__ __forceinline__ uint32_t pack_bf2(float x, float y) {
    uint16_t lx = __bfloat16_as_ushort(__float2bfloat16_rn(x));
    uint16_t ly = __bfloat16_as_ushort(__float2bfloat16_rn(y));
    return (uint32_t)lx | ((uint32_t)ly << 16);
}

__device__ __forceinline__ void split2(float x, float y, uint32_t& hw, uint32_t& lw) {
    float hx = __bfloat162float(__float2bfloat16_rn(x));
    float hy = __bfloat162float(__float2bfloat16_rn(y));
    hw = pack_bf2(hx, hy);
    lw = pack_bf2(x - hx, y - hy);
}

__device__ __forceinline__ float fast_exp2(float x) {
    float y;
    asm("ex2.approx.f32 %0, %1;" : "=f"(y) : "f"(x));
    return y;
}

// ---------------------------------------------------------------------------
// Kernel 0: split pre-pass. Converts an fp32 tensor into packed bf16 hi/lo
// word arrays (device-resolved destinations). which: 0/1/2 = q/k/v input,
// 3 = in_proj_w, 4 = out_w.
// ---------------------------------------------------------------------------
__global__ void __launch_bounds__(256) split_pass(const float4* __restrict__ src,
                                                  int which, int nf4)
{
    int i = blockIdx.x * blockDim.x + threadIdx.x;
    if (i >= nf4) return;
    float4 v = src[i];
    uint32_t h0, l0, h1, l1;
    split2(v.x, v.y, h0, l0);
    split2(v.z, v.w, h1, l1);
    uint32_t *dh, *dl;
    size_t off = 2 * (size_t)i;
    if (which < 3)      { dh = g_inh + (size_t)which * M_ROWS * CW;
                          dl = g_inl + (size_t)which * M_ROWS * CW; }
    else if (which == 3){ dh = g_wih; dl = g_wil; }
    else                { dh = g_woh; dl = g_wol; }
    dh[off] = h0; dh[off + 1] = h1;
    dl[off] = l0; dl[off + 1] = l1;
}

// ---------------------------------------------------------------------------
// Tensor-core GEMM, 3xBF16, operands pre-split in gmem (pure LDG->STS fill):
//   C[m][j] = sum_c A[m][c]*W[j][c] + bias[j]
// Tile 128x128, BK=32, single-sync double buffer, 8 warps (2x4), 64x32 warp
// tiles. Smem rows: 16 data words + 4 pad (proven conflict-free).
// mode 0: z picks q/k/v; scatter q/k fp32 head layout, v transposed bf16.
// mode 1: A = g_xh/g_xl, linear fp32 store to dlin.
// ---------------------------------------------------------------------------
#define SW      20
#define PLANE_W (128 * SW)
#define STAGE_W (4 * PLANE_W)            // Ah, Al, Bh, Bl
#define GEMM_SMEM_BYTES (2 * STAGE_W * 4)   // 81920 bytes

__global__ void __launch_bounds__(256, 2) gemm_tc(
    const float* __restrict__ bias, float* __restrict__ dlin, int mode)
{
    extern __shared__ uint32_t sg[];

    const int z = blockIdx.z;
    const uint32_t* Agh = (mode == 1) ? g_xh : g_inh + (size_t)z * M_ROWS * CW;
    const uint32_t* Agl = (mode == 1) ? g_xl : g_inl + (size_t)z * M_ROWS * CW;
    const uint32_t* Bgh = (mode == 1) ? g_woh : g_wih + (size_t)z * 1024 * CW;
    const uint32_t* Bgl = (mode == 1) ? g_wol : g_wil + (size_t)z * 1024 * CW;
    const float* bp = bias + z * C_DIM;

    const int m0 = blockIdx.y * 128;
    const int n0 = blockIdx.x * 128;
    const int tid  = threadIdx.x;
    const int wid  = tid >> 5;
    const int lane = tid & 31;
    const int warp_m = wid >> 2;
    const int warp_n = wid & 3;
    const int g   = lane >> 2;
    const int tig = lane & 3;

    float acc[4][4][4];
#pragma unroll
    for (int i = 0; i < 4; i++)
#pragma unroll
        for (int j = 0; j < 4; j++)
#pragma unroll
            for (int c = 0; c < 4; c++) acc[i][j][c] = 0.f;

    // fill indices: f = tid + 256u (u<2): row f>>2, word4 (f&3)*4
    const int fr = tid >> 2;
    const int fc = (tid & 3) << 2;
    uint4 pah[2], pal[2], pbh[2], pbl[2];

#define LDG_TILE(kit) {                                                          \
        int _kw = (kit) * 16;                                                    \
        _Pragma("unroll")                                                        \
        for (int u = 0; u < 2; u++) {                                            \
            int r = fr + 64 * u;                                                 \
            size_t ao = (size_t)(m0 + r) * CW + _kw + fc;                        \
            size_t bo = (size_t)(n0 + r) * CW + _kw + fc;                        \
            pah[u] = *(const uint4*)&Agh[ao];  pal[u] = *(const uint4*)&Agl[ao]; \
            pbh[u] = *(const uint4*)&Bgh[bo];  pbl[u] = *(const uint4*)&Bgl[bo]; \
        }                                                                        \
    }

#define STS_TILE(s) {                                                            \
        uint32_t* Ah = sg + (s) * STAGE_W;                                       \
        uint32_t* Al = Ah + PLANE_W;                                             \
        uint32_t* Bh = Ah + 2 * PLANE_W;                                         \
        uint32_t* Bl = Ah + 3 * PLANE_W;                                         \
        _Pragma("unroll")                                                        \
        for (int u = 0; u < 2; u++) {                                            \
            int w = (fr + 64 * u) * SW + fc;                                     \
            *(uint4*)&Ah[w] = pah[u];  *(uint4*)&Al[w] = pal[u];                 \
            *(uint4*)&Bh[w] = pbh[u];  *(uint4*)&Bl[w] = pbl[u];                 \
        }                                                                        \
    }

    const int NIT = C_DIM / 32;   // 32

    LDG_TILE(0);
    STS_TILE(0);
    __syncthreads();

    for (int it = 0; it < NIT; it++) {
        const int s = it & 1;
        const bool pf = (it + 1 < NIT);
        if (pf) LDG_TILE(it + 1);

        const uint32_t* Ah = sg + s * STAGE_W;
        const uint32_t* Al = Ah + PLANE_W;
        const uint32_t* Bh = Ah + 2 * PLANE_W;
        const uint32_t* Bl = Ah + 3 * PLANE_W;

#pragma unroll
        for (int ks = 0; ks < 2; ks++) {
            const int kw = ks * 8 + tig;

            uint32_t bh[4][2], bl[4][2];
#pragma unroll
            for (int n8 = 0; n8 < 4; n8++) {
                int nb = (warp_n * 32 + n8 * 8 + g) * SW;
                bh[n8][0] = Bh[nb + kw];  bh[n8][1] = Bh[nb + kw + 4];
                bl[n8][0] = Bl[nb + kw];  bl[n8][1] = Bl[nb + kw + 4];
            }
#pragma unroll
            for (int mt = 0; mt < 4; mt++) {
                int rb = (warp_m * 64 + mt * 16 + g) * SW;
                uint32_t ah[4], al[4];
                ah[0] = Ah[rb + kw];            ah[1] = Ah[rb + 8 * SW + kw];
                ah[2] = Ah[rb + kw + 4];        ah[3] = Ah[rb + 8 * SW + kw + 4];
                al[0] = Al[rb + kw];            al[1] = Al[rb + 8 * SW + kw];
                al[2] = Al[rb + kw + 4];        al[3] = Al[rb + 8 * SW + kw + 4];
#pragma unroll
                for (int n8 = 0; n8 < 4; n8++) {
                    mma_bf16(acc[mt][n8], ah, bh[n8][0], bh[n8][1]);  // hi*hi
                    mma_bf16(acc[mt][n8], ah, bl[n8][0], bl[n8][1]);  // hi*lo
                    mma_bf16(acc[mt][n8], al, bh[n8][0], bh[n8][1]);  // lo*hi
                }
            }
        }
        if (pf) STS_TILE(s ^ 1);
        __syncthreads();
    }

    // Epilogue. D frag: c0,c1 = (row g, cols 2tig,2tig+1); c2,c3 = row+8.
    const int erow = lane >> 2;
    const int ecol = (lane & 3) * 2;
#pragma unroll
    for (int mt = 0; mt < 4; mt++) {
#pragma unroll
        for (int nt = 0; nt < 4; nt++) {
            int col = n0 + warp_n * 32 + nt * 8 + ecol;
            float bx = bp[col], by = bp[col + 1];
#pragma unroll
            for (int half = 0; half < 2; half++) {
                int m = m0 + warp_m * 64 + mt * 16 + erow + half * 8;
                float v0 = acc[mt][nt][half * 2 + 0] + bx;
                float v1 = acc[mt][nt][half * 2 + 1] + by;
                if (mode == 0) {
                    int n = m >> 2, bb = m & 3;     // row m = n*B + b
                    int h = col >> 6, d = col & 63;
                    if (z == 2) {
                        size_t base = ((size_t)(bb * H_NUM + h) * HD + d) * N_SEQ + n;
                        float h0 = __bfloat162float(__float2bfloat16_rn(v0));
                        float h1 = __bfloat162float(__float2bfloat16_rn(v1));
                        g_vh16[base]         = __float2bfloat16_rn(v0);
                        g_vl16[base]         = __float2bfloat16_rn(v0 - h0);
                        g_vh16[base + N_SEQ] = __float2bfloat16_rn(v1);
                        g_vl16[base + N_SEQ] = __float2bfloat16_rn(v1 - h1);
                    } else {
                        float* outp = (z == 0) ? g_qs : g_ks;
                        float2 v = { v0, v1 };
                        *(float2*)(outp + (((size_t)(bb * H_NUM + h) * N_SEQ) + n) * HD + d) = v;
                    }
                } else {
                    float2 v = { v0, v1 };
                    *(float2*)(dlin + (size_t)m * C_DIM + col) = v;
                }
            }
        }
    }
#undef LDG_TILE
#undef STS_TILE
}

// ---------------------------------------------------------------------------
// Kernel 2: L2-normalize q/k rows, fold exp(min(ls,log100))*log2e into q,
// emit packed bf16 hi/lo words. One warp per row.
// ---------------------------------------------------------------------------
__global__ void __launch_bounds__(256) norm_kernel(const float* __restrict__ logit_scale)
{
    int wrow = (blockIdx.x * blockDim.x + threadIdx.x) >> 5;
    int lane = threadIdx.x & 31;
    const int rows_per_tensor = BH * N_SEQ;  // 65536
    if (wrow >= 2 * rows_per_tensor) return;
    int which = wrow >= rows_per_tensor;
    int row = wrow - which * rows_per_tensor;   // = bh*N + n
    const float* ptr = (which ? g_ks : g_qs) + (size_t)row * HD;

    float x0 = ptr[2 * lane];
    float x1 = ptr[2 * lane + 1];
    float ss = x0 * x0 + x1 * x1;
#pragma unroll
    for (int o = 16; o > 0; o >>= 1) ss += __shfl_xor_sync(0xffffffffu, ss, o);
    float scale = 1.0f / fmaxf(sqrtf(ss), 1e-12f);
    if (!which) {
        int h = (row >> 10) & 15;
        scale *= expf(fminf(logit_scale[h], LOGMAX)) * LOG2E;  // base-2 softmax
    }
    uint32_t hw, lw;
    split2(x0 * scale, x1 * scale, hw, lw);
    uint32_t* dh = which ? g_kh : g_qh;
    uint32_t* dl = which ? g_kl : g_ql;
    dh[(size_t)row * 32 + lane] = hw;
    dl[(size_t)row * 32 + lane] = lw;
}

// ---------------------------------------------------------------------------
// Kernel 3: tensor-core flash attention. Block = 128 q x one head; 8 warps,
// each owns 16 complete query rows. Epilogue writes split bf16 g_x.
// ---------------------------------------------------------------------------
#define AW    36
#define Q_H   0
#define Q_L   (128 * AW)
#define K_H   (2 * 128 * AW)
#define K_L   (K_H + 64 * AW)
#define V_H   (K_L + 64 * AW)
#define V_L   (V_H + 64 * AW)
#define ATTN_SMEM_WORDS (V_L + 64 * AW)
#define ATTN_SMEM_BYTES (ATTN_SMEM_WORDS * 4)        // 73728 bytes

__global__ void __launch_bounds__(256, 2) attn_kernel()
{
    extern __shared__ uint32_t sa[];

    const int bh = blockIdx.y;
    const int n0 = blockIdx.x * 128;
    const int tid  = threadIdx.x;
    const int warp = tid >> 5;
    const int lane = tid & 31;
    const int g    = lane >> 2;
    const int tig  = lane & 3;
    const int qr   = warp * 16;

    const size_t qrow0 = (size_t)bh * N_SEQ + n0;
    const size_t krow0 = (size_t)bh * N_SEQ;
    const size_t vrow0 = (size_t)bh * HD;
    const uint32_t* vwh = (const uint32_t*)g_vh16;
    const uint32_t* vwl = (const uint32_t*)g_vl16;

#pragma unroll
    for (int u = 0; u < 4; u++) {
        int f = tid + 256 * u;
        int r = f >> 3, w4 = (f & 7) << 2;
        *(uint4*)&sa[Q_H + r * AW + w4] = *(const uint4*)&g_qh[(qrow0 + r) * 32 + w4];
        *(uint4*)&sa[Q_L + r * AW + w4] = *(const uint4*)&g_ql[(qrow0 + r) * 32 + w4];
    }

    float m0 = -1e30f, m1 = -1e30f, l0 = 0.f, l1 = 0.f;
    float o_acc[8][4];
#pragma unroll
    for (int i = 0; i < 8; i++)
#pragma unroll
        for (int c = 0; c < 4; c++) o_acc[i][c] = 0.f;

    for (int kt = 0; kt < N_SEQ / 64; kt++) {
        __syncthreads();
#pragma unroll
        for (int u = 0; u < 2; u++) {
            int f = tid + 256 * u;
            int r = f >> 3, w4 = (f & 7) << 2;
            *(uint4*)&sa[K_H + r * AW + w4] = *(const uint4*)&g_kh[(krow0 + kt * 64 + r) * 32 + w4];
            *(uint4*)&sa[K_L + r * AW + w4] = *(const uint4*)&g_kl[(krow0 + kt * 64 + r) * 32 + w4];
            *(uint4*)&sa[V_H + r * AW + w4] = *(const uint4*)&vwh[(vrow0 + r) * 512 + kt * 32 + w4];
            *(uint4*)&sa[V_L + r * AW + w4] = *(const uint4*)&vwl[(vrow0 + r) * 512 + kt * 32 + w4];
        }
        __syncthreads();

        // ---- S = Q K^T, 3xbf16 ----
        float s_acc[8][4];
#pragma unroll
        for (int i = 0; i < 8; i++)
#pragma unroll
            for (int c = 0; c < 4; c++) s_acc[i][c] = 0.f;

#pragma unroll
        for (int s = 0; s < 4; s++) {
            const int kw = s * 8 + tig;
            const int rb = (qr + g) * AW;
            uint32_t qh[4], ql[4];
            qh[0] = sa[Q_H + rb + kw];          qh[1] = sa[Q_H + rb + 8 * AW + kw];
            qh[2] = sa[Q_H + rb + kw + 4];      qh[3] = sa[Q_H + rb + 8 * AW + kw + 4];
            ql[0] = sa[Q_L + rb + kw];          ql[1] = sa[Q_L + rb + 8 * AW + kw];
            ql[2] = sa[Q_L + rb + kw + 4];      ql[3] = sa[Q_L + rb + 8 * AW + kw + 4];
#pragma unroll
            for (int nt = 0; nt < 8; nt++) {
                int kb = (nt * 8 + g) * AW;
                uint32_t kh0 = sa[K_H + kb + kw], kh1 = sa[K_H + kb + kw + 4];
                uint32_t kl0 = sa[K_L + kb + kw], kl1 = sa[K_L + kb + kw + 4];
                mma_bf16(s_acc[nt], qh, kh0, kh1);
                mma_bf16(s_acc[nt], qh, kl0, kl1);
                mma_bf16(s_acc[nt], ql, kh0, kh1);
            }
        }

        // ---- online softmax (base-2) ----
        float rmax0 = -1e30f, rmax1 = -1e30f;
#pragma unroll
        for (int nt = 0; nt < 8; nt++) {
            rmax0 = fmaxf(rmax0, fmaxf(s_acc[nt][0], s_acc[nt][1]));
            rmax1 = fmaxf(rmax1, fmaxf(s_acc[nt][2], s_acc[nt][3]));
        }
        rmax0 = fmaxf(rmax0, __shfl_xor_sync(0xffffffffu, rmax0, 1));
        rmax0 = fmaxf(rmax0, __shfl_xor_sync(0xffffffffu, rmax0, 2));
        rmax1 = fmaxf(rmax1, __shfl_xor_sync(0xffffffffu, rmax1, 1));
        rmax1 = fmaxf(rmax1, __shfl_xor_sync(0xffffffffu, rmax1, 2));
        float mn0 = fmaxf(m0, rmax0), mn1 = fmaxf(m1, rmax1);
        float corr0 = fast_exp2(m0 - mn0), corr1 = fast_exp2(m1 - mn1);
        float rs0 = 0.f, rs1 = 0.f;
#pragma unroll
        for (int nt = 0; nt < 8; nt++) {
            s_acc[nt][0] = fast_exp2(s_acc[nt][0] - mn0);
            s_acc[nt][1] = fast_exp2(s_acc[nt][1] - mn0);
            s_acc[nt][2] = fast_exp2(s_acc[nt][2] - mn1);
            s_acc[nt][3] = fast_exp2(s_acc[nt][3] - mn1);
            rs0 += s_acc[nt][0] + s_acc[nt][1];
            rs1 += s_acc[nt][2] + s_acc[nt][3];
        }
        rs0 += __shfl_xor_sync(0xffffffffu, rs0, 1);
        rs0 += __shfl_xor_sync(0xffffffffu, rs0, 2);
        rs1 += __shfl_xor_sync(0xffffffffu, rs1, 1);
        rs1 += __shfl_xor_sync(0xffffffffu, rs1, 2);
        l0 = l0 * corr0 + rs0;  m0 = mn0;
        l1 = l1 * corr1 + rs1;  m1 = mn1;
#pragma unroll
        for (int nt = 0; nt < 8; nt++) {
            o_acc[nt][0] *= corr0;  o_acc[nt][1] *= corr0;
            o_acc[nt][2] *= corr1;  o_acc[nt][3] *= corr1;
        }

        // ---- O += P V ----
#pragma unroll
        for (int s = 0; s < 4; s++) {
            uint32_t pah[4], pal[4];
            split2(s_acc[2 * s][0],     s_acc[2 * s][1],     pah[0], pal[0]);
            split2(s_acc[2 * s][2],     s_acc[2 * s][3],     pah[1], pal[1]);
            split2(s_acc[2 * s + 1][0], s_acc[2 * s + 1][1], pah[2], pal[2]);
            split2(s_acc[2 * s + 1][2], s_acc[2 * s + 1][3], pah[3], pal[3]);
            const int kw = s * 8 + tig;
#pragma unroll
            for (int nt = 0; nt < 8; nt++) {
                int vb = (nt * 8 + g) * AW;
                uint32_t vh0 = sa[V_H + vb + kw], vh1 = sa[V_H + vb + kw + 4];
                uint32_t vl0 = sa[V_L + vb + kw], vl1 = sa[V_L + vb + kw + 4];
                mma_bf16(o_acc[nt], pah, vh0, vh1);
                mma_bf16(o_acc[nt], pah, vl0, vl1);
                mma_bf16(o_acc[nt], pal, vh0, vh1);
            }
        }
    }

    // Epilogue: out[q][d] = o/l, stored pre-split for the output projection
    const int bb = bh >> 4;
    const int h  = bh & 15;
    float inv0 = 1.0f / l0, inv1 = 1.0f / l1;
    int nq0 = n0 + qr + g;
    size_t row0 = ((size_t)nq0 * B_SZ + bb) * CW;
    size_t row1 = ((size_t)(nq0 + 8) * B_SZ + bb) * CW;
#pragma unroll
    for (int nt = 0; nt < 8; nt++) {
        int w = h * 32 + nt * 4 + tig;
        uint32_t hw, lw;
        split2(o_acc[nt][0] * inv0, o_acc[nt][1] * inv0, hw, lw);
        g_xh[row0 + w] = hw;  g_xl[row0 + w] = lw;
        split2(o_acc[nt][2] * inv1, o_acc[nt][3] * inv1, hw, lw);
        g_xh[row1 + w] = hw;  g_xl[row1 + w] = lw;
    }
}

// ---------------------------------------------------------------------------
extern "C" void kernel_launch(void* const* d_in, const int* in_sizes, int n_in,
                              void* d_out, int out_size)
{
    const float* q     = (const float*)d_in[0];
    const float* k     = (const float*)d_in[1];
    const float* v     = (const float*)d_in[2];
    const float* w_in  = (const float*)d_in[3];
    const float* b_in  = (const float*)d_in[4];
    const float* ls    = (const float*)d_in[5];
    const float* w_out = (const float*)d_in[6];
    const float* b_out = (const float*)d_in[7];
    float* out = (float*)d_out;

    cudaFuncSetAttribute(gemm_tc,
                         cudaFuncAttributeMaxDynamicSharedMemorySize,
                         GEMM_SMEM_BYTES);
    cudaFuncSetAttribute(attn_kernel,
                         cudaFuncAttributeMaxDynamicSharedMemorySize,
                         ATTN_SMEM_BYTES);

    const int nf4_in = M_ROWS * C_DIM / 4;      // 1048576
    const int nf4_wi = 3 * 1024 * C_DIM / 4;    // 786432
    const int nf4_wo = 1024 * C_DIM / 4;        // 262144
    split_pass<<<nf4_in / 256, 256>>>((const float4*)q,     0, nf4_in);
    split_pass<<<nf4_in / 256, 256>>>((const float4*)k,     1, nf4_in);
    split_pass<<<nf4_in / 256, 256>>>((const float4*)v,     2, nf4_in);
    split_pass<<<nf4_wi / 256, 256>>>((const float4*)w_in,  3, nf4_wi);
    split_pass<<<nf4_wo / 256, 256>>>((const float4*)w_out, 4, nf4_wo);

    gemm_tc<<<dim3(C_DIM / 128, M_ROWS / 128, 3), 256, GEMM_SMEM_BYTES>>>(
        b_in, nullptr, 0);
    norm_kernel<<<(2 * BH * N_SEQ) / 8, 256>>>(ls);
    attn_kernel<<<dim3(N_SEQ / 128, BH), 256, ATTN_SMEM_BYTES>>>();
    gemm_tc<<<dim3(C_DIM / 128, M_ROWS / 128, 1), 256, GEMM_SMEM_BYTES>>>(
        b_out, out, 1);
}